// round 3
// baseline (speedup 1.0000x reference)
#include <cuda_runtime.h>

#define NQ 16
#define BATCH 512

// Per-(wire, sample) precomputed tables (L2-resident, ~80 KB)
__device__ float4 tabV[NQ][BATCH];  // v0x v0y v1x v1y  (v_w = RY(th0)RX(x)|0>)
__device__ float2 tabG[NQ][BATCH];  // (C1, S1) = (cos th1, sin th1)  [full angle]
__device__ float  tabN[NQ][BATCH];  // |v0|^2 - |v1|^2 = cos(th0) * cos(x)

// ---------------------------------------------------------------------------
// Pre-kernel: 16 wires x 512 samples, one thread per (w, b).
// ---------------------------------------------------------------------------
__global__ void __launch_bounds__(128) k_pre(const float* __restrict__ x,
                                             const float* __restrict__ p) {
    const int t = blockIdx.x * blockDim.x + threadIdx.x;   // 0..8191
    const int w = t >> 9;
    const int b = t & 511;
    float sx, cx; __sincosf(0.5f * x[b * NQ + w], &sx, &cx);
    float s0, c0; __sincosf(0.5f * p[w],          &s0, &c0);
    float s1, c1; __sincosf(p[NQ + w],            &s1, &c1);
    tabV[w][b] = make_float4(c0 * cx, s0 * sx, s0 * cx, -c0 * sx);
    tabG[w][b] = make_float2(c1, s1);
    tabN[w][b] = (c0 * c0 - s0 * s0) * (cx * cx - sx * sx);
}

// One signed transfer step: f <- D o (B f B^H),
//   B = [[v0, v1], [v1, v0]],  D = [[C, -S], [-S, -C]]
__device__ __forceinline__ void signed_step(float fr[2][2], float fi[2][2],
                                            const float4 V, const float2 G) {
    const float v0x = V.x, v0y = V.y, v1x = V.z, v1y = V.w;
    float gr[2][2], gi[2][2];
    #pragma unroll
    for (int c = 0; c < 2; c++) {
        gr[0][c] = v0x*fr[0][c] - v0y*fi[0][c] + v1x*fr[1][c] - v1y*fi[1][c];
        gi[0][c] = v0x*fi[0][c] + v0y*fr[0][c] + v1x*fi[1][c] + v1y*fr[1][c];
        gr[1][c] = v1x*fr[0][c] - v1y*fi[0][c] + v0x*fr[1][c] - v0y*fi[1][c];
        gi[1][c] = v1x*fi[0][c] + v1y*fr[0][c] + v0x*fi[1][c] + v0y*fr[1][c];
    }
    float hr[2][2], hi[2][2];
    #pragma unroll
    for (int Q = 0; Q < 2; Q++) {
        hr[Q][0] = gr[Q][0]*v0x + gi[Q][0]*v0y + gr[Q][1]*v1x + gi[Q][1]*v1y;
        hi[Q][0] = gi[Q][0]*v0x - gr[Q][0]*v0y + gi[Q][1]*v1x - gr[Q][1]*v1y;
        hr[Q][1] = gr[Q][0]*v1x + gi[Q][0]*v1y + gr[Q][1]*v0x + gi[Q][1]*v0y;
        hi[Q][1] = gi[Q][0]*v1x - gr[Q][0]*v1y + gi[Q][1]*v0x - gr[Q][1]*v0y;
    }
    const float C = G.x, S = G.y;
    fr[0][0] =  C * hr[0][0];  fi[0][0] =  C * hi[0][0];
    fr[0][1] = -S * hr[0][1];  fi[0][1] = -S * hi[0][1];
    fr[1][0] = -S * hr[1][0];  fi[1][0] = -S * hi[1][0];
    fr[1][1] = -C * hr[1][1];  fi[1][1] = -C * hi[1][1];
}

// Re(a * f * conj(b)) for complex a=(ax,ay), f=(fx,fy), b=(bx,by)
__device__ __forceinline__ float reafb(float ax, float ay, float fx, float fy,
                                       float bx, float by) {
    return (ax * fx - ay * fy) * bx + (ax * fy + ay * fx) * by;
}

// ---------------------------------------------------------------------------
// Main kernel: warp-uniform m.
//   Warps 0..447   : m = 1..14, lanes = 16 samples x 2 boundaries (P=P')
//                    m signed steps + 1 diag step + scalar suffix tail.
//   Warps 448..575 : m = 0 / 15, lanes = 8 samples x 4 boundaries (P,P'),
//                    15 signed steps.
// ---------------------------------------------------------------------------
__global__ void __launch_bounds__(128) k_main(float* __restrict__ out) {
    const int W    = blockIdx.x * 4 + (threadIdx.x >> 5);
    const int lane = threadIdx.x & 31;
    float fr[2][2], fi[2][2];

    if (W < 448) {
        const int m = 1 + (W >> 5);
        const int b = ((W & 31) << 4) + (lane >> 1);
        const int P = lane & 1;

        {   // wire-0 init (signed), boundary (P, P)
            const float4 V = tabV[0][b];
            const float2 G = tabG[0][b];
            float rr[2][2], ri[2][2];
            rr[0][0] = V.x*V.x + V.y*V.y;  ri[0][0] = 0.f;
            rr[0][1] = V.x*V.z + V.y*V.w;  ri[0][1] = V.y*V.z - V.x*V.w;
            rr[1][0] = rr[0][1];           ri[1][0] = -ri[0][1];
            rr[1][1] = V.z*V.z + V.w*V.w;  ri[1][1] = 0.f;
            #pragma unroll
            for (int q = 0; q < 2; q++)
                #pragma unroll
                for (int qp = 0; qp < 2; qp++) {
                    const int a = P ^ q, c = P ^ qp;
                    const float d = (a == c) ? (a ? -G.x : G.x) : -G.y;
                    fr[q][qp] = rr[q][qp] * d;
                    fi[q][qp] = ri[q][qp] * d;
                }
        }

        for (int w = 1; w <= m; ++w)
            signed_step(fr, fi, tabV[w][b], tabG[w][b]);

        // first unsigned step (w = m+1): only real diagonal survives
        const float4 U = tabV[m + 1][b];
        const float d0 = reafb(U.x, U.y, fr[0][0], fi[0][0], U.x, U.y)
                       + reafb(U.x, U.y, fr[0][1], fi[0][1], U.z, U.w)
                       + reafb(U.z, U.w, fr[1][0], fi[1][0], U.x, U.y)
                       + reafb(U.z, U.w, fr[1][1], fi[1][1], U.z, U.w);
        const float d1 = reafb(U.z, U.w, fr[0][0], fi[0][0], U.z, U.w)
                       + reafb(U.z, U.w, fr[0][1], fi[0][1], U.x, U.y)
                       + reafb(U.x, U.y, fr[1][0], fi[1][0], U.z, U.w)
                       + reafb(U.x, U.y, fr[1][1], fi[1][1], U.x, U.y);

        // scalar tail: t scales by suffix product of ndiff, s invariant
        float suf = 1.f;
        for (int w = m + 2; w < NQ; ++w) suf *= tabN[w][b];
        const float s  = d0 + d1;
        const float tt = (d0 - d1) * suf;
        float val = 0.5f * (P ? (s - tt) : (s + tt));
        val += __shfl_xor_sync(0xFFFFFFFFu, val, 1);
        if (!P) out[b * NQ + m] = val;
    } else {
        const int E   = W - 448;
        const int m15 = (E >> 6);                 // 0 -> m=0, 1 -> m=15
        const int b   = ((E & 63) << 3) + (lane >> 2);
        const int P   = lane & 1;
        const int Pp  = (lane >> 1) & 1;

        {   // wire-0 init, boundary (P, Pp); m=0 -> identity D0, m=15 -> signed
            const float4 V = tabV[0][b];
            const float2 G = tabG[0][b];
            float rr[2][2], ri[2][2];
            rr[0][0] = V.x*V.x + V.y*V.y;  ri[0][0] = 0.f;
            rr[0][1] = V.x*V.z + V.y*V.w;  ri[0][1] = V.y*V.z - V.x*V.w;
            rr[1][0] = rr[0][1];           ri[1][0] = -ri[0][1];
            rr[1][1] = V.z*V.z + V.w*V.w;  ri[1][1] = 0.f;
            #pragma unroll
            for (int q = 0; q < 2; q++)
                #pragma unroll
                for (int qp = 0; qp < 2; qp++) {
                    const int a = P ^ q, c = Pp ^ qp;
                    float d;
                    if (m15) d = (a == c) ? (a ? -G.x : G.x) : -G.y;
                    else     d = (a == c) ? 1.f : 0.f;
                    fr[q][qp] = rr[q][qp] * d;
                    fi[q][qp] = ri[q][qp] * d;
                }
        }

        #pragma unroll 3
        for (int w = 1; w < NQ; ++w)
            signed_step(fr, fi, tabV[w][b], tabG[w][b]);

        float val = P ? (Pp ? fr[1][1] : fr[1][0])
                      : (Pp ? fr[0][1] : fr[0][0]);
        val += __shfl_xor_sync(0xFFFFFFFFu, val, 1);
        val += __shfl_xor_sync(0xFFFFFFFFu, val, 2);
        if ((lane & 3) == 0) out[b * NQ + (m15 ? 15 : 0)] = val;
    }
}

extern "C" void kernel_launch(void* const* d_in, const int* in_sizes, int n_in,
                              void* d_out, int out_size) {
    (void)in_sizes; (void)n_in; (void)out_size;
    const float* x      = (const float*)d_in[0];
    const float* params = (const float*)d_in[1];
    float* out = (float*)d_out;

    k_pre <<<64, 128>>>(x, params);
    k_main<<<144, 128>>>(out);
}

// round 4
// speedup vs baseline: 1.6000x; 1.6000x over previous
#include <cuda_runtime.h>

#define NQ 16
#define BATCH 512

// Single-kernel exact transfer-matrix evaluation (bond density, 4-dim).
// Per CTA: 4 samples. 36 chains/sample (m=1..14: 2 diag boundary terms;
// m=0,15: 4 boundary terms), all running 15 uniform select-coefficient steps.
__global__ void __launch_bounds__(160) k_expval(const float* __restrict__ x,
                                                const float* __restrict__ p,
                                                float* __restrict__ out) {
    __shared__ float4 sV[4][NQ];   // v0x v0y v1x v1y
    __shared__ float2 sG[4][NQ];   // (cos th1, sin th1) full angle

    const int tid = threadIdx.x;

    // ---- prologue: 4 samples x 16 wires, fast sincos ----
    if (tid < 64) {
        const int w  = tid & 15;
        const int bl = tid >> 4;
        const int b  = blockIdx.x * 4 + bl;
        float sx, cx; __sincosf(0.5f * x[b * NQ + w], &sx, &cx);
        float s0, c0; __sincosf(0.5f * p[w],          &s0, &c0);
        float s1, c1; __sincosf(p[NQ + w],            &s1, &c1);
        sV[bl][w] = make_float4(c0 * cx, s0 * sx, s0 * cx, -c0 * sx);
        sG[bl][w] = make_float2(c1, s1);
    }
    __syncthreads();

    // ---- chain assignment ----
    int bl  = tid / 36;           // 0..3 (4 = padding lanes)
    const int cid = tid - bl * 36;
    if (bl > 3) bl = 3;           // clamp padding lanes (their stores are off)
    const bool pad = (tid >= 144);

    int m, P, Pp;
    if (cid < 28)      { m = 1 + (cid >> 1); P = cid & 1;  Pp = P; }
    else if (cid < 32) { m = 0;  P = cid & 1; Pp = (cid >> 1) & 1; }
    else               { m = 15; P = cid & 1; Pp = (cid >> 1) & 1; }

    float fr[2][2], fi[2][2];

    // ---- wire-0 init: f0 = D0 o (v conj(v)^T), boundary (P, Pp) ----
    {
        const float4 V = sV[bl][0];
        const float2 G = sG[bl][0];
        const bool  sg = (m >= 1);                 // wire 0 signed iff m>=1
        const float m00 = sg ?  G.x : 1.f;
        const float m01 = sg ? -G.y : 0.f;
        const float m11 = sg ? -G.x : 1.f;

        float rr[2][2], ri[2][2];
        rr[0][0] = V.x * V.x + V.y * V.y;  ri[0][0] = 0.f;
        rr[0][1] = V.x * V.z + V.y * V.w;  ri[0][1] = V.y * V.z - V.x * V.w;
        rr[1][0] = rr[0][1];               ri[1][0] = -ri[0][1];
        rr[1][1] = V.z * V.z + V.w * V.w;  ri[1][1] = 0.f;

        #pragma unroll
        for (int q = 0; q < 2; q++)
            #pragma unroll
            for (int qp = 0; qp < 2; qp++) {
                const int a = P ^ q, c = Pp ^ qp;
                const float d = (a == c) ? (a ? m11 : m00) : m01;
                fr[q][qp] = rr[q][qp] * d;
                fi[q][qp] = ri[q][qp] * d;
            }
    }

    // ---- wires 1..15: f <- M o (B f B^H), M via selects (no divergence) ----
    #pragma unroll
    for (int w = 1; w < NQ; w++) {
        const float4 V = sV[bl][w];
        const float2 G = sG[bl][w];
        const bool  sg = (m == 0) || (w <= m);
        const float m00 = sg ?  G.x : 1.f;
        const float m01 = sg ? -G.y : 0.f;
        const float m11 = sg ? -G.x : 1.f;
        const float v0x = V.x, v0y = V.y, v1x = V.z, v1y = V.w;

        float gr[2][2], gi[2][2];
        #pragma unroll
        for (int c = 0; c < 2; c++) {
            gr[0][c] = v0x*fr[0][c] - v0y*fi[0][c] + v1x*fr[1][c] - v1y*fi[1][c];
            gi[0][c] = v0x*fi[0][c] + v0y*fr[0][c] + v1x*fi[1][c] + v1y*fr[1][c];
            gr[1][c] = v1x*fr[0][c] - v1y*fi[0][c] + v0x*fr[1][c] - v0y*fi[1][c];
            gi[1][c] = v1x*fi[0][c] + v1y*fr[0][c] + v0x*fi[1][c] + v0y*fr[1][c];
        }
        float hr00, hi00, hr01, hi01, hr10, hi10, hr11, hi11;
        hr00 = gr[0][0]*v0x + gi[0][0]*v0y + gr[0][1]*v1x + gi[0][1]*v1y;
        hi00 = gi[0][0]*v0x - gr[0][0]*v0y + gi[0][1]*v1x - gr[0][1]*v1y;
        hr01 = gr[0][0]*v1x + gi[0][0]*v1y + gr[0][1]*v0x + gi[0][1]*v0y;
        hi01 = gi[0][0]*v1x - gr[0][0]*v1y + gi[0][1]*v0x - gr[0][1]*v0y;
        hr10 = gr[1][0]*v0x + gi[1][0]*v0y + gr[1][1]*v1x + gi[1][1]*v1y;
        hi10 = gi[1][0]*v0x - gr[1][0]*v0y + gi[1][1]*v1x - gr[1][1]*v1y;
        hr11 = gr[1][0]*v1x + gi[1][0]*v1y + gr[1][1]*v0x + gi[1][1]*v0y;
        hi11 = gi[1][0]*v1x - gr[1][0]*v1y + gi[1][1]*v0x - gr[1][1]*v0y;

        fr[0][0] = m00 * hr00;  fi[0][0] = m00 * hi00;
        fr[0][1] = m01 * hr01;  fi[0][1] = m01 * hi01;
        fr[1][0] = m01 * hr10;  fi[1][0] = m01 * hi10;
        fr[1][1] = m11 * hr11;  fi[1][1] = m11 * hi11;
    }

    // ---- readout + uniform reduction ----
    float val = P ? (Pp ? fr[1][1] : fr[1][0])
                  : (Pp ? fr[0][1] : fr[0][0]);

    const float v1s = val + __shfl_xor_sync(0xFFFFFFFFu, val, 1);
    const float v2s = v1s + __shfl_xor_sync(0xFFFFFFFFu, v1s, 2);

    if (!pad) {
        const int b = blockIdx.x * 4 + bl;
        if (cid < 28) {
            if ((cid & 1) == 0) out[b * NQ + m] = v1s;     // pair sum
        } else {
            if ((cid & 3) == 0) out[b * NQ + m] = v2s;     // quad sum
        }
    }
}

extern "C" void kernel_launch(void* const* d_in, const int* in_sizes, int n_in,
                              void* d_out, int out_size) {
    (void)in_sizes; (void)n_in; (void)out_size;
    const float* x      = (const float*)d_in[0];
    const float* params = (const float*)d_in[1];
    float* out = (float*)d_out;

    k_expval<<<128, 160>>>(x, params, out);
}

// round 5
// speedup vs baseline: 1.6618x; 1.0386x over previous
#include <cuda_runtime.h>

#define NQ 16
#define BATCH 512

// Hermitian-parametrized transfer-matrix chains: state (a, d, r, s).
// 36 chains/sample: m=1..14 diag pairs (28), m=0 quad (2 diag + fH + zero),
// m=15 quad (2 diag + fH + antiHerm g).
__global__ void __launch_bounds__(160) k_expval(const float* __restrict__ x,
                                                const float* __restrict__ p,
                                                float* __restrict__ out) {
    __shared__ float4 sK[4][NQ];   // n0, wx, wy, nd    (n1 = n0 - nd)
    __shared__ float2 sG[4][NQ];   // C = cos th1, S = sin th1

    const int tid = threadIdx.x;

    // ---- prologue: 4 samples x 16 wires ----
    if (tid < 64) {
        const int w  = tid & 15;
        const int bl = tid >> 4;
        const int b  = blockIdx.x * 4 + bl;
        float sxf, cxf; __sincosf(x[b * NQ + w], &sxf, &cxf);
        float s0f, c0f; __sincosf(p[w],          &s0f, &c0f);
        float S,   C;   __sincosf(p[NQ + w],     &S,   &C);
        const float nd = c0f * cxf;
        sK[bl][w] = make_float4(0.5f * (1.f + nd), 0.5f * s0f * cxf,
                                0.5f * sxf,        nd);
        sG[bl][w] = make_float2(C, S);
    }
    __syncthreads();

    // ---- chain assignment (same layout as round 4) ----
    int bl = tid / 36;
    const int cid = tid - bl * 36;
    if (bl > 3) bl = 3;
    const bool pad = (tid >= 144);

    // meff: last signed wire (wires w<=meff signed; wire 0 handled in init)
    const int m    = (cid < 28) ? (1 + (cid >> 1)) : ((cid < 32) ? 0 : 15);
    const int meff = (cid < 28) ? m : 15;
    const int typ  = (cid < 28) ? (cid & 1) : (cid & 3);  // 0:a 1:d 2:2r 3:-2s

    float a, d, r, s;

    // ---- wire-0 init ----
    {
        const float4 K = sK[bl][0];
        const float2 G = sG[bl][0];
        const float n0 = K.x, wx = K.y, wy = K.z;
        const float n1 = n0 - K.w;
        const float C = G.x, S = G.y;

        if (cid < 28) {            // diag chain, wire 0 signed
            const int P = cid & 1;
            a = P ? -n0 * C :  n0 * C;
            d = P ?  n1 * C : -n1 * C;
            r = -S * wx;  s = -S * wy;
        } else if (cid < 32) {     // m = 0 (wire 0 unsigned)
            switch (typ) {
                case 0: case 1: a = n0;  d = n1;  r = 0.f; s = 0.f; break;
                case 2:         a = 0.f; d = 0.f; r = wx;  s = wy;  break;
                default:        a = 0.f; d = 0.f; r = 0.f; s = 0.f; break;
            }
        } else {                   // m = 15 (wire 0 signed)
            switch (typ) {
                case 0: a =  n0 * C; d = -n1 * C; r = -S * wx; s = -S * wy; break;
                case 1: a = -n0 * C; d =  n1 * C; r = -S * wx; s = -S * wy; break;
                case 2: a = -S * n0; d = -S * n1; r = 0.f;     s = 0.f;     break;
                default:a = 0.f;     d = 0.f;     r = C * wy;  s = -C * wx; break;
            }
        }
    }

    // ---- wires 1..15 ----
    #pragma unroll
    for (int w = 1; w < NQ; w++) {
        const float4 K = sK[bl][w];
        const float2 G = sG[bl][w];
        const float n0 = K.x, wx = K.y, wy = K.z, nd = K.w;
        const float n1 = n0 - nd;
        const bool sg = (w <= meff);
        const float m00 = sg ?  G.x : 1.f;
        const float m01 = sg ? -G.y : 0.f;
        const float m11 = sg ? -G.x : 1.f;

        const float q1 = wx * r, q2 = wy * s;
        const float t2 = q1 - q2 + q1 - q2;       // 2(wx r - wy s)
        const float u2 = q1 + q2 + q1 + q2;       // 2(wx r + wy s)
        const float ha = fmaf(n0, a, fmaf(n1, d, t2));
        const float hd = fmaf(n1, a, fmaf(n0, d, u2));
        const float hr = fmaf(a + d, wx, r);
        const float hs = fmaf(a - d, wy, nd * s);
        a = m00 * ha;  d = m11 * hd;
        r = m01 * hr;  s = m01 * hs;
    }

    // ---- readout + reductions ----
    float val;
    switch (typ) {
        case 0:  val = a;            break;
        case 1:  val = d;            break;
        case 2:  val = r + r;        break;
        default: val = -(s + s);     break;
    }

    const float v1s = val + __shfl_xor_sync(0xFFFFFFFFu, val, 1);
    const float v2s = v1s + __shfl_xor_sync(0xFFFFFFFFu, v1s, 2);

    if (!pad) {
        const int b = blockIdx.x * 4 + bl;
        if (cid < 28) {
            if ((cid & 1) == 0) out[b * NQ + m] = v1s;
        } else {
            if ((cid & 3) == 0) out[b * NQ + m] = v2s;
        }
    }
}

extern "C" void kernel_launch(void* const* d_in, const int* in_sizes, int n_in,
                              void* d_out, int out_size) {
    (void)in_sizes; (void)n_in; (void)out_size;
    const float* x      = (const float*)d_in[0];
    const float* params = (const float*)d_in[1];
    float* out = (float*)d_out;

    k_expval<<<128, 160>>>(x, params, out);
}